// round 3
// baseline (speedup 1.0000x reference)
#include <cuda_runtime.h>
#include <math.h>

#define HD 128
#define TILE 64      // edges per block tile
#define NTILE 64     // nodes per block tile (pre)
#define OTILE 32     // nodes per block tile (out)
#define NMAX 20000
#define EMAX 640000

// Scratch (device globals: allocation-free)
__device__ float g_P[NMAX * HD];
__device__ float g_Q[NMAX * HD];
__device__ float g_mi[NMAX * HD];
__device__ float g_psum[NMAX * 3];
__device__ float g_cnt[NMAX];

__device__ __forceinline__ float silu(float x) {
    return x / (1.0f + __expf(-x));
}

// ---------------------------------------------------------------- zero
__global__ void zero_kernel(int N) {
    int i = blockIdx.x * blockDim.x + threadIdx.x;
    if (i < N * HD) g_mi[i] = 0.0f;
    int j = i - N * HD;
    if (j >= 0 && j < N * 3) g_psum[j] = 0.0f;
    int k = i - N * (HD + 3);
    if (k >= 0 && k < N) g_cnt[k] = 0.0f;
}

// ---------------------------------------------------------------- node pre:
// P = h @ eW1[0:128,:], Q = h @ eW1[128:256,:]   (weights streamed from L1/L2)
__global__ __launch_bounds__(256) void node_pre_kernel(
    const float* __restrict__ h, const float* __restrict__ eW1, int N)
{
    __shared__ float sH[NTILE * HD];   // 32 KB

    const int base = blockIdx.x * NTILE;

    for (int idx = threadIdx.x; idx < NTILE * HD; idx += 256) {
        int n = base + (idx >> 7);
        sH[idx] = (n < N) ? h[(size_t)n * HD + (idx & 127)] : 0.0f;
    }
    __syncthreads();

    const int lane = threadIdx.x & 31;
    const int warp = threadIdx.x >> 5;
    const int jj = lane * 4;
    const int e0 = warp * 8;           // 8 nodes per warp

    #pragma unroll
    for (int half = 0; half < 2; half++) {
        const float* W = eW1 + (size_t)half * HD * HD;
        float* out = half ? g_Q : g_P;

        float acc[8][4];
        #pragma unroll
        for (int e = 0; e < 8; e++)
            #pragma unroll
            for (int i = 0; i < 4; i++) acc[e][i] = 0.f;

        for (int k = 0; k < HD; k += 4) {
            float4 w0 = *(const float4*)&W[(k + 0) * HD + jj];
            float4 w1 = *(const float4*)&W[(k + 1) * HD + jj];
            float4 w2 = *(const float4*)&W[(k + 2) * HD + jj];
            float4 w3 = *(const float4*)&W[(k + 3) * HD + jj];
            #pragma unroll
            for (int e = 0; e < 8; e++) {
                float4 tv = *(const float4*)&sH[(e0 + e) * HD + k];
                acc[e][0] = fmaf(tv.x, w0.x, acc[e][0]);
                acc[e][1] = fmaf(tv.x, w0.y, acc[e][1]);
                acc[e][2] = fmaf(tv.x, w0.z, acc[e][2]);
                acc[e][3] = fmaf(tv.x, w0.w, acc[e][3]);
                acc[e][0] = fmaf(tv.y, w1.x, acc[e][0]);
                acc[e][1] = fmaf(tv.y, w1.y, acc[e][1]);
                acc[e][2] = fmaf(tv.y, w1.z, acc[e][2]);
                acc[e][3] = fmaf(tv.y, w1.w, acc[e][3]);
                acc[e][0] = fmaf(tv.z, w2.x, acc[e][0]);
                acc[e][1] = fmaf(tv.z, w2.y, acc[e][1]);
                acc[e][2] = fmaf(tv.z, w2.z, acc[e][2]);
                acc[e][3] = fmaf(tv.z, w2.w, acc[e][3]);
                acc[e][0] = fmaf(tv.w, w3.x, acc[e][0]);
                acc[e][1] = fmaf(tv.w, w3.y, acc[e][1]);
                acc[e][2] = fmaf(tv.w, w3.z, acc[e][2]);
                acc[e][3] = fmaf(tv.w, w3.w, acc[e][3]);
            }
        }
        #pragma unroll
        for (int e = 0; e < 8; e++) {
            int n = base + e0 + e;
            if (n < N) {
                float4 o = make_float4(acc[e][0], acc[e][1], acc[e][2], acc[e][3]);
                *(float4*)&out[(size_t)n * HD + jj] = o;
            }
        }
    }
}

// ---------------------------------------------------------------- edge kernel
__global__ __launch_bounds__(256) void edge_kernel(
    const float* __restrict__ pos,
    const int* __restrict__ eidx,                 // int32! (JAX x64 disabled)
    const float* __restrict__ eW1, const float* __restrict__ eb1,
    const float* __restrict__ eW2, const float* __restrict__ eb2,
    const float* __restrict__ cW1, const float* __restrict__ cb1,
    const float* __restrict__ cW2,
    int N, int E)
{
    __shared__ float TM[TILE * HD];    // 32 KB, T then overwritten with M
    __shared__ float sSq[TILE], sCw[TILE], sDx[TILE], sDy[TILE], sDz[TILE];
    __shared__ int   sR[TILE], sC[TILE];

    const int base = blockIdx.x * TILE;

    if (threadIdx.x < TILE) {
        int e = base + threadIdx.x;
        int r = 0, c = 0;
        float dx = 0.f, dy = 0.f, dz = 0.f, sq = 0.f;
        if (e < E) {
            r = eidx[e];
            c = eidx[E + e];
            dx = pos[r * 3 + 0] - pos[c * 3 + 0];
            dy = pos[r * 3 + 1] - pos[c * 3 + 1];
            dz = pos[r * 3 + 2] - pos[c * 3 + 2];
            sq = dx * dx + dy * dy + dz * dz;
        }
        sR[threadIdx.x] = r; sC[threadIdx.x] = c;
        sSq[threadIdx.x] = sq;
        sDx[threadIdx.x] = dx; sDy[threadIdx.x] = dy; sDz[threadIdx.x] = dz;
    }
    __syncthreads();

    // assembly: T = silu(P[r] + Q[c] + sq*eW1[256,:] + eb1)
    for (int idx = threadIdx.x; idx < TILE * HD; idx += 256) {
        int e = idx >> 7, j = idx & 127;
        int r = sR[e], c = sC[e];
        float x = g_P[(size_t)r * HD + j] + g_Q[(size_t)c * HD + j]
                + sSq[e] * eW1[256 * HD + j] + eb1[j];
        TM[idx] = silu(x);
    }
    __syncthreads();

    const int lane = threadIdx.x & 31;
    const int warp = threadIdx.x >> 5;
    const int jj = lane * 4;
    const int e0 = warp * 8;

    // GEMV 1: M = silu(T @ eW2 + eb2); overwrite TM rows in place
    {
        float acc[8][4];
        #pragma unroll
        for (int e = 0; e < 8; e++)
            #pragma unroll
            for (int i = 0; i < 4; i++) acc[e][i] = 0.f;

        for (int k = 0; k < HD; k += 4) {
            float4 w0 = *(const float4*)&eW2[(k + 0) * HD + jj];
            float4 w1 = *(const float4*)&eW2[(k + 1) * HD + jj];
            float4 w2 = *(const float4*)&eW2[(k + 2) * HD + jj];
            float4 w3 = *(const float4*)&eW2[(k + 3) * HD + jj];
            #pragma unroll
            for (int e = 0; e < 8; e++) {
                float4 tv = *(const float4*)&TM[(e0 + e) * HD + k];
                acc[e][0] = fmaf(tv.x, w0.x, acc[e][0]);
                acc[e][1] = fmaf(tv.x, w0.y, acc[e][1]);
                acc[e][2] = fmaf(tv.x, w0.z, acc[e][2]);
                acc[e][3] = fmaf(tv.x, w0.w, acc[e][3]);
                acc[e][0] = fmaf(tv.y, w1.x, acc[e][0]);
                acc[e][1] = fmaf(tv.y, w1.y, acc[e][1]);
                acc[e][2] = fmaf(tv.y, w1.z, acc[e][2]);
                acc[e][3] = fmaf(tv.y, w1.w, acc[e][3]);
                acc[e][0] = fmaf(tv.z, w2.x, acc[e][0]);
                acc[e][1] = fmaf(tv.z, w2.y, acc[e][1]);
                acc[e][2] = fmaf(tv.z, w2.z, acc[e][2]);
                acc[e][3] = fmaf(tv.z, w2.w, acc[e][3]);
                acc[e][0] = fmaf(tv.w, w3.x, acc[e][0]);
                acc[e][1] = fmaf(tv.w, w3.y, acc[e][1]);
                acc[e][2] = fmaf(tv.w, w3.z, acc[e][2]);
                acc[e][3] = fmaf(tv.w, w3.w, acc[e][3]);
            }
        }
        __syncwarp();   // all lanes done reading T rows before overwrite
        float4 b2 = *(const float4*)&eb2[jj];
        #pragma unroll
        for (int e = 0; e < 8; e++) {
            float4 mo;
            mo.x = silu(acc[e][0] + b2.x);
            mo.y = silu(acc[e][1] + b2.y);
            mo.z = silu(acc[e][2] + b2.z);
            mo.w = silu(acc[e][3] + b2.w);
            *(float4*)&TM[(e0 + e) * HD + jj] = mo;   // in-place: own rows only
        }
    }
    __syncwarp();

    // GEMV 2: cw = silu(M @ cW1 + cb1) . cW2
    {
        float acc[8][4];
        #pragma unroll
        for (int e = 0; e < 8; e++)
            #pragma unroll
            for (int i = 0; i < 4; i++) acc[e][i] = 0.f;

        for (int k = 0; k < HD; k += 4) {
            float4 w0 = *(const float4*)&cW1[(k + 0) * HD + jj];
            float4 w1 = *(const float4*)&cW1[(k + 1) * HD + jj];
            float4 w2 = *(const float4*)&cW1[(k + 2) * HD + jj];
            float4 w3 = *(const float4*)&cW1[(k + 3) * HD + jj];
            #pragma unroll
            for (int e = 0; e < 8; e++) {
                float4 tv = *(const float4*)&TM[(e0 + e) * HD + k];
                acc[e][0] = fmaf(tv.x, w0.x, acc[e][0]);
                acc[e][1] = fmaf(tv.x, w0.y, acc[e][1]);
                acc[e][2] = fmaf(tv.x, w0.z, acc[e][2]);
                acc[e][3] = fmaf(tv.x, w0.w, acc[e][3]);
                acc[e][0] = fmaf(tv.y, w1.x, acc[e][0]);
                acc[e][1] = fmaf(tv.y, w1.y, acc[e][1]);
                acc[e][2] = fmaf(tv.y, w1.z, acc[e][2]);
                acc[e][3] = fmaf(tv.y, w1.w, acc[e][3]);
                acc[e][0] = fmaf(tv.z, w2.x, acc[e][0]);
                acc[e][1] = fmaf(tv.z, w2.y, acc[e][1]);
                acc[e][2] = fmaf(tv.z, w2.z, acc[e][2]);
                acc[e][3] = fmaf(tv.z, w2.w, acc[e][3]);
                acc[e][0] = fmaf(tv.w, w3.x, acc[e][0]);
                acc[e][1] = fmaf(tv.w, w3.y, acc[e][1]);
                acc[e][2] = fmaf(tv.w, w3.z, acc[e][2]);
                acc[e][3] = fmaf(tv.w, w3.w, acc[e][3]);
            }
        }
        float4 cb  = *(const float4*)&cb1[jj];
        float4 cw2 = *(const float4*)&cW2[jj];
        #pragma unroll
        for (int e = 0; e < 8; e++) {
            float p = silu(acc[e][0] + cb.x) * cw2.x
                    + silu(acc[e][1] + cb.y) * cw2.y
                    + silu(acc[e][2] + cb.z) * cw2.z
                    + silu(acc[e][3] + cb.w) * cw2.w;
            #pragma unroll
            for (int off = 16; off > 0; off >>= 1)
                p += __shfl_xor_sync(0xFFFFFFFFu, p, off);
            if (lane == 0) sCw[e0 + e] = p;
        }
    }
    __syncthreads();

    // scatter messages (TM now holds M)
    for (int idx = threadIdx.x; idx < TILE * HD; idx += 256) {
        int e = idx >> 7, j = idx & 127;
        if (base + e < E)
            atomicAdd(&g_mi[(size_t)sR[e] * HD + j], TM[idx]);
    }
    // scatter pos updates + counts
    if (threadIdx.x < TILE) {
        int e = threadIdx.x;
        if (base + e < E) {
            float inv = rsqrtf(sSq[e] + 1e-8f);
            float w = sCw[e] * inv;
            int r = sR[e];
            atomicAdd(&g_psum[r * 3 + 0], sDx[e] * w);
            atomicAdd(&g_psum[r * 3 + 1], sDy[e] * w);
            atomicAdd(&g_psum[r * 3 + 2], sDz[e] * w);
            atomicAdd(&g_cnt[r], 1.0f);
        }
    }
}

// ---------------------------------------------------------------- node out MLP + pos
__global__ __launch_bounds__(256) void node_out_kernel(
    const float* __restrict__ h, const float* __restrict__ pos,
    const float* __restrict__ nW1, const float* __restrict__ nb1,
    const float* __restrict__ nW2, const float* __restrict__ nb2,
    float* __restrict__ outH, float* __restrict__ outP, int N)
{
    __shared__ float sX[OTILE * 2 * HD];   // 32 KB

    const int base = blockIdx.x * OTILE;

    for (int idx = threadIdx.x; idx < OTILE * 2 * HD; idx += 256) {
        int n = base + (idx >> 8);
        int j = idx & 255;
        float v = 0.f;
        if (n < N)
            v = (j < HD) ? h[(size_t)n * HD + j] : g_mi[(size_t)n * HD + (j - HD)];
        sX[idx] = v;
    }
    __syncthreads();

    const int lane = threadIdx.x & 31;
    const int warp = threadIdx.x >> 5;
    const int jj = lane * 4;
    const int e0 = warp * 4;           // 4 nodes per warp

    // GEMV 1: U = silu([h|m] @ nW1 + nb1), in-place into cols [0,128)
    {
        float acc[4][4];
        #pragma unroll
        for (int e = 0; e < 4; e++)
            #pragma unroll
            for (int i = 0; i < 4; i++) acc[e][i] = 0.f;

        for (int k = 0; k < 2 * HD; k += 4) {
            float4 w0 = *(const float4*)&nW1[(k + 0) * HD + jj];
            float4 w1 = *(const float4*)&nW1[(k + 1) * HD + jj];
            float4 w2 = *(const float4*)&nW1[(k + 2) * HD + jj];
            float4 w3 = *(const float4*)&nW1[(k + 3) * HD + jj];
            #pragma unroll
            for (int e = 0; e < 4; e++) {
                float4 tv = *(const float4*)&sX[(e0 + e) * 2 * HD + k];
                acc[e][0] = fmaf(tv.x, w0.x, acc[e][0]);
                acc[e][1] = fmaf(tv.x, w0.y, acc[e][1]);
                acc[e][2] = fmaf(tv.x, w0.z, acc[e][2]);
                acc[e][3] = fmaf(tv.x, w0.w, acc[e][3]);
                acc[e][0] = fmaf(tv.y, w1.x, acc[e][0]);
                acc[e][1] = fmaf(tv.y, w1.y, acc[e][1]);
                acc[e][2] = fmaf(tv.y, w1.z, acc[e][2]);
                acc[e][3] = fmaf(tv.y, w1.w, acc[e][3]);
                acc[e][0] = fmaf(tv.z, w2.x, acc[e][0]);
                acc[e][1] = fmaf(tv.z, w2.y, acc[e][1]);
                acc[e][2] = fmaf(tv.z, w2.z, acc[e][2]);
                acc[e][3] = fmaf(tv.z, w2.w, acc[e][3]);
                acc[e][0] = fmaf(tv.w, w3.x, acc[e][0]);
                acc[e][1] = fmaf(tv.w, w3.y, acc[e][1]);
                acc[e][2] = fmaf(tv.w, w3.z, acc[e][2]);
                acc[e][3] = fmaf(tv.w, w3.w, acc[e][3]);
            }
        }
        __syncwarp();
        float4 b1 = *(const float4*)&nb1[jj];
        #pragma unroll
        for (int e = 0; e < 4; e++) {
            float4 u;
            u.x = silu(acc[e][0] + b1.x);
            u.y = silu(acc[e][1] + b1.y);
            u.z = silu(acc[e][2] + b1.z);
            u.w = silu(acc[e][3] + b1.w);
            *(float4*)&sX[(e0 + e) * 2 * HD + jj] = u;   // in-place: own rows only
        }
    }
    __syncwarp();

    // GEMV 2: out = h + U @ nW2 + nb2
    {
        float acc[4][4];
        #pragma unroll
        for (int e = 0; e < 4; e++)
            #pragma unroll
            for (int i = 0; i < 4; i++) acc[e][i] = 0.f;

        for (int k = 0; k < HD; k += 4) {
            float4 w0 = *(const float4*)&nW2[(k + 0) * HD + jj];
            float4 w1 = *(const float4*)&nW2[(k + 1) * HD + jj];
            float4 w2 = *(const float4*)&nW2[(k + 2) * HD + jj];
            float4 w3 = *(const float4*)&nW2[(k + 3) * HD + jj];
            #pragma unroll
            for (int e = 0; e < 4; e++) {
                float4 tv = *(const float4*)&sX[(e0 + e) * 2 * HD + k];
                acc[e][0] = fmaf(tv.x, w0.x, acc[e][0]);
                acc[e][1] = fmaf(tv.x, w0.y, acc[e][1]);
                acc[e][2] = fmaf(tv.x, w0.z, acc[e][2]);
                acc[e][3] = fmaf(tv.x, w0.w, acc[e][3]);
                acc[e][0] = fmaf(tv.y, w1.x, acc[e][0]);
                acc[e][1] = fmaf(tv.y, w1.y, acc[e][1]);
                acc[e][2] = fmaf(tv.y, w1.z, acc[e][2]);
                acc[e][3] = fmaf(tv.y, w1.w, acc[e][3]);
                acc[e][0] = fmaf(tv.z, w2.x, acc[e][0]);
                acc[e][1] = fmaf(tv.z, w2.y, acc[e][1]);
                acc[e][2] = fmaf(tv.z, w2.z, acc[e][2]);
                acc[e][3] = fmaf(tv.z, w2.w, acc[e][3]);
                acc[e][0] = fmaf(tv.w, w3.x, acc[e][0]);
                acc[e][1] = fmaf(tv.w, w3.y, acc[e][1]);
                acc[e][2] = fmaf(tv.w, w3.z, acc[e][2]);
                acc[e][3] = fmaf(tv.w, w3.w, acc[e][3]);
            }
        }
        float4 b2 = *(const float4*)&nb2[jj];
        #pragma unroll
        for (int e = 0; e < 4; e++) {
            int n = base + e0 + e;
            if (n < N) {
                float4 hv = *(const float4*)&h[(size_t)n * HD + jj];
                float4 o;
                o.x = hv.x + acc[e][0] + b2.x;
                o.y = hv.y + acc[e][1] + b2.y;
                o.z = hv.z + acc[e][2] + b2.z;
                o.w = hv.w + acc[e][3] + b2.w;
                *(float4*)&outH[(size_t)n * HD + jj] = o;
            }
        }
    }

    // pos update
    if (threadIdx.x < OTILE) {
        int n = base + threadIdx.x;
        if (n < N) {
            float c = fmaxf(g_cnt[n], 1.0f);
            outP[n * 3 + 0] = pos[n * 3 + 0] + g_psum[n * 3 + 0] / c;
            outP[n * 3 + 1] = pos[n * 3 + 1] + g_psum[n * 3 + 1] / c;
            outP[n * 3 + 2] = pos[n * 3 + 2] + g_psum[n * 3 + 2] / c;
        }
    }
}

// ---------------------------------------------------------------- launch
extern "C" void kernel_launch(void* const* d_in, const int* in_sizes, int n_in,
                              void* d_out, int out_size)
{
    const float* h    = (const float*)d_in[0];
    const float* pos  = (const float*)d_in[1];
    const int*   eidx = (const int*)d_in[2];      // int32 (JAX default x64 off)
    const float* eW1  = (const float*)d_in[3];
    const float* eb1  = (const float*)d_in[4];
    const float* eW2  = (const float*)d_in[5];
    const float* eb2  = (const float*)d_in[6];
    const float* cW1  = (const float*)d_in[7];
    const float* cb1  = (const float*)d_in[8];
    const float* cW2  = (const float*)d_in[9];
    const float* nW1  = (const float*)d_in[10];
    const float* nb1  = (const float*)d_in[11];
    const float* nW2  = (const float*)d_in[12];
    const float* nb2  = (const float*)d_in[13];

    const int N = in_sizes[0] / HD;
    const int E = in_sizes[2] / 2;

    float* outH = (float*)d_out;
    float* outP = outH + (size_t)N * HD;

    zero_kernel<<<(N * (HD + 4) + 255) / 256, 256>>>(N);
    node_pre_kernel<<<(N + NTILE - 1) / NTILE, 256>>>(h, eW1, N);
    edge_kernel<<<(E + TILE - 1) / TILE, 256>>>(pos, eidx, eW1, eb1, eW2, eb2,
                                                cW1, cb1, cW2, N, E);
    node_out_kernel<<<(N + OTILE - 1) / OTILE, 256>>>(h, pos, nW1, nb1, nW2, nb2,
                                                      outH, outP, N);
}